// round 6
// baseline (speedup 1.0000x reference)
#include <cuda_runtime.h>
#include <math.h>

// Triplet-margin ranking loss, GB300 sm_103a — fused streaming kernel.
// d_ap computed ONCE by block 0; consumers buffer per-row d_an and only
// consult the published d_ap AFTER their streaming loop (no mid-loop sync).
// anchor: (1, 2400) f32, positive: (P=5, 2400) f32, negative: (100000, 2400) f32
// loss = sum_{i<num_full} relu(d_ap[i % P] - d_an[i] + MARGIN)
// d_x = || anchor - x + EPS ||_2  (elementwise +EPS, torch pairwise_distance)

#define EPS      1e-6f
#define MARGIN   1.0f
#define DIM      2400
#define DIM4     (DIM / 4)   // 600 float4 per row
#define MAX_ROWS 16          // max rows per warp (100000 / 9728 = 10.3 -> <=11)

__device__ float        g_dap[8];   // d_ap values (P <= 8; problem has P=5)
__device__ volatile int g_flag;     // release flag; reset by memset each launch

// ---------------------------------------------------------------------------
__global__ void __launch_bounds__(256, 8)
loss_kernel(const float* __restrict__ anchor,
            const float* __restrict__ pos,
            const float* __restrict__ neg,
            float* __restrict__ out,
            int num_full, int P)
{
    __shared__ float4 sA[DIM4];        // anchor, 9600 B
    __shared__ float  sWarp[8];

    const int wid  = threadIdx.x >> 5;
    const int lane = threadIdx.x & 31;

    // ---- stage anchor into shared (all blocks) ----
    const float4* a4 = reinterpret_cast<const float4*>(anchor);
    for (int k = threadIdx.x; k < DIM4; k += blockDim.x)
        sA[k] = a4[k];

    // ---- block 0 only: compute d_ap (48 KB read ONCE chip-wide) ----
    if (blockIdx.x == 0 && wid < P) {
        const float4* p4 = reinterpret_cast<const float4*>(pos + (size_t)wid * DIM);
        float s = 0.0f;
        #pragma unroll 4
        for (int k = lane; k < DIM4; k += 32) {
            float4 a = a4[k];            // anchor from global (smem not synced yet)
            float4 p = __ldg(&p4[k]);
            float d0 = a.x - p.x + EPS;
            float d1 = a.y - p.y + EPS;
            float d2 = a.z - p.z + EPS;
            float d3 = a.w - p.w + EPS;
            s = fmaf(d0, d0, s);
            s = fmaf(d1, d1, s);
            s = fmaf(d2, d2, s);
            s = fmaf(d3, d3, s);
        }
        #pragma unroll
        for (int o = 16; o > 0; o >>= 1)
            s += __shfl_xor_sync(0xFFFFFFFFu, s, o);
        if (lane == 0) g_dap[wid] = sqrtf(s);
        // release: one thread of block 0 publishes after its warp finishes.
        // All P dap warps must be done -> publish after syncthreads below.
    }
    __syncthreads();                     // anchor staged; block0: d_ap written

    if (blockIdx.x == 0 && threadIdx.x == 0) {
        __threadfence();                 // publish g_dap
        g_flag = 1;                      // release (~5us into the kernel)
    }

    // ---- static warp-per-row grid-stride over negatives ----
    // No d_ap dependency inside this loop: lane 0 buffers d_an per row.
    const int nwarps = blockDim.x >> 5;
    const int gwarp  = blockIdx.x * nwarps + wid;
    const int W      = gridDim.x * nwarps;

    float pend[MAX_ROWS];                // lane 0 only (others never indexed)
    int   cnt = 0;

    for (int row = gwarp; row < num_full; row += W) {
        const float4* n4 = reinterpret_cast<const float4*>(neg + (size_t)row * DIM);
        float s = 0.0f;
        // 600 float4 / 32 lanes = 18.75 iterations; unroll for MLP
        #pragma unroll 4
        for (int k = lane; k < DIM4; k += 32) {
            float4 a = sA[k];
            float4 n = __ldg(&n4[k]);
            float d0 = a.x - n.x + EPS;
            float d1 = a.y - n.y + EPS;
            float d2 = a.z - n.z + EPS;
            float d3 = a.w - n.w + EPS;
            s = fmaf(d0, d0, s);
            s = fmaf(d1, d1, s);
            s = fmaf(d2, d2, s);
            s = fmaf(d3, d3, s);
        }
        #pragma unroll
        for (int o = 16; o > 0; o >>= 1)
            s += __shfl_xor_sync(0xFFFFFFFFu, s, o);
        if (lane == 0)
            pend[cnt++] = sqrtf(s);      // defer: d_ap applied after the loop
    }

    // ---- drain: flag was set ~5us in, we are ~140us in -> poll hits once ----
    float acc = 0.0f;
    if (lane == 0 && cnt > 0) {
        while (g_flag == 0) { __nanosleep(100); }
        __threadfence();                 // acquire
        float dapl[8];
        #pragma unroll
        for (int j = 0; j < 8; j++)
            dapl[j] = *((volatile float*)&g_dap[j]);

        int row = gwarp;
        for (int i = 0; i < cnt; i++, row += W) {
            float t = dapl[row % P] - pend[i] + MARGIN;
            acc += (t > 0.0f) ? t : 0.0f;
        }
    }

    // ---- block reduction + single atomic ----
    if (lane == 0) sWarp[wid] = acc;
    __syncthreads();
    if (threadIdx.x == 0) {
        float bsum = 0.0f;
        #pragma unroll
        for (int i = 0; i < 8; i++) bsum += sWarp[i];
        atomicAdd(out, bsum);
    }
}

// ---------------------------------------------------------------------------
extern "C" void kernel_launch(void* const* d_in, const int* in_sizes, int n_in,
                              void* d_out, int out_size)
{
    const float* anchor = (const float*)d_in[0];
    const float* pos    = (const float*)d_in[1];
    const float* neg    = (const float*)d_in[2];
    float* out = (float*)d_out;

    const int P = in_sizes[1] / DIM;          // 5
    const int N = in_sizes[2] / DIM;          // 100000
    const int num_full = (N / P) * P;         // 100000

    // zero the poisoned output scalar + the release flag (graph-capturable)
    cudaMemsetAsync(d_out, 0, sizeof(float));
    void* flag_addr = nullptr;
    cudaGetSymbolAddress(&flag_addr, g_flag);
    cudaMemsetAsync(flag_addr, 0, sizeof(int));

    // one resident wave: 8 blocks of 256 threads per SM
    int sm_count = 148;
    cudaDeviceGetAttribute(&sm_count, cudaDevAttrMultiProcessorCount, 0);
    const int grid = sm_count * 8;
    loss_kernel<<<grid, 256>>>(anchor, pos, neg, out, num_full, P);
}

// round 7
// speedup vs baseline: 1.1638x; 1.1638x over previous
#include <cuda_runtime.h>
#include <math.h>

// Triplet-margin ranking loss, GB300 sm_103a.
// Two-kernel structure (fused variants measured SLOWER in R3/R4/R6):
//   dap_kernel: P blocks, one positive row each (~3us)
//   loss_kernel: byte-identical to the R1 champion body (141.0us measured)
// anchor: (1, 2400) f32, positive: (P=5, 2400) f32, negative: (100000, 2400) f32
// loss = sum_{i<num_full} relu(d_ap[i % P] - d_an[i] + MARGIN)
// d_x = || anchor - x + EPS ||_2  (elementwise +EPS, torch pairwise_distance)

#define EPS    1e-6f
#define MARGIN 1.0f
#define DIM    2400
#define DIM4   (DIM / 4)   // 600 float4 per row

// d_ap values (P <= 8 supported; problem has P = 5)
__device__ float g_dap[8];

// ---------------------------------------------------------------------------
// Kernel 1: block b computes d_ap[b] (one positive row per block, 256 thr).
// ---------------------------------------------------------------------------
__global__ void __launch_bounds__(256)
dap_kernel(const float* __restrict__ anchor,
           const float* __restrict__ pos,
           int P)
{
    __shared__ float sred[8];
    const int b    = blockIdx.x;
    const int wid  = threadIdx.x >> 5;
    const int lane = threadIdx.x & 31;

    if (b >= P) return;

    const float4* a4 = reinterpret_cast<const float4*>(anchor);
    const float4* p4 = reinterpret_cast<const float4*>(pos + (size_t)b * DIM);
    float s = 0.0f;
    for (int k = threadIdx.x; k < DIM4; k += blockDim.x) {
        float4 a = a4[k];
        float4 p = p4[k];
        float d0 = a.x - p.x + EPS;
        float d1 = a.y - p.y + EPS;
        float d2 = a.z - p.z + EPS;
        float d3 = a.w - p.w + EPS;
        s = fmaf(d0, d0, s);
        s = fmaf(d1, d1, s);
        s = fmaf(d2, d2, s);
        s = fmaf(d3, d3, s);
    }
    #pragma unroll
    for (int o = 16; o > 0; o >>= 1)
        s += __shfl_xor_sync(0xFFFFFFFFu, s, o);
    if (lane == 0) sred[wid] = s;
    __syncthreads();
    if (threadIdx.x == 0) {
        float t = 0.0f;
        #pragma unroll
        for (int i = 0; i < 8; i++) t += sred[i];
        g_dap[b] = sqrtf(t);
    }
}

// ---------------------------------------------------------------------------
// Kernel 2: streaming over negative rows. Warp-per-row, grid-stride, STATIC.
// Anchor staged in shared (9.6 KB). One atomicAdd per block.
// (Identical to the R1 champion: 141.0us, DRAM 86.2%.)
// ---------------------------------------------------------------------------
__global__ void __launch_bounds__(256, 8)
loss_kernel(const float* __restrict__ anchor,
            const float* __restrict__ neg,
            float* __restrict__ out,
            int num_full, int P)
{
    __shared__ float4 sA[DIM4];        // anchor, 9600 B
    __shared__ float  sDap[8];
    __shared__ float  sWarp[8];

    // stage anchor into shared
    const float4* a4 = reinterpret_cast<const float4*>(anchor);
    for (int k = threadIdx.x; k < DIM4; k += blockDim.x)
        sA[k] = a4[k];
    if (threadIdx.x < 8)
        sDap[threadIdx.x] = (threadIdx.x < P) ? g_dap[threadIdx.x] : 0.0f;
    __syncthreads();

    const int wid    = threadIdx.x >> 5;
    const int lane   = threadIdx.x & 31;
    const int nwarps = blockDim.x >> 5;
    const int gwarp  = blockIdx.x * nwarps + wid;
    const int W      = gridDim.x * nwarps;

    float acc = 0.0f;

    for (int row = gwarp; row < num_full; row += W) {
        const float4* n4 = reinterpret_cast<const float4*>(neg + (size_t)row * DIM);
        float s = 0.0f;
        // 600 float4 / 32 lanes = 18.75 iterations; unroll for MLP
        #pragma unroll 4
        for (int k = lane; k < DIM4; k += 32) {
            float4 a = sA[k];
            float4 n = __ldg(&n4[k]);
            float d0 = a.x - n.x + EPS;
            float d1 = a.y - n.y + EPS;
            float d2 = a.z - n.z + EPS;
            float d3 = a.w - n.w + EPS;
            s = fmaf(d0, d0, s);
            s = fmaf(d1, d1, s);
            s = fmaf(d2, d2, s);
            s = fmaf(d3, d3, s);
        }
        #pragma unroll
        for (int o = 16; o > 0; o >>= 1)
            s += __shfl_xor_sync(0xFFFFFFFFu, s, o);
        if (lane == 0) {
            float d_an = sqrtf(s);
            float t = sDap[row % P] - d_an + MARGIN;
            acc += (t > 0.0f) ? t : 0.0f;
        }
    }

    // block reduction: lane 0 of each warp holds its partial
    if (lane == 0) sWarp[wid] = acc;
    __syncthreads();
    if (threadIdx.x == 0) {
        float b = 0.0f;
        for (int i = 0; i < nwarps; i++) b += sWarp[i];
        atomicAdd(out, b);
    }
}

// ---------------------------------------------------------------------------
extern "C" void kernel_launch(void* const* d_in, const int* in_sizes, int n_in,
                              void* d_out, int out_size)
{
    const float* anchor = (const float*)d_in[0];
    const float* pos    = (const float*)d_in[1];
    const float* neg    = (const float*)d_in[2];
    float* out = (float*)d_out;

    const int P = in_sizes[1] / DIM;          // 5
    const int N = in_sizes[2] / DIM;          // 100000
    const int num_full = (N / P) * P;         // 100000

    // zero the poisoned output scalar (graph-capturable async memset)
    cudaMemsetAsync(d_out, 0, sizeof(float));

    dap_kernel<<<(P > 0 ? P : 1), 256>>>(anchor, pos, P);

    // 1184 blocks of 256 threads: the measured-fastest shape (R1: 141.0us)
    const int grid = 148 * 8;
    loss_kernel<<<grid, 256>>>(anchor, neg, out, num_full, P);
}